// round 16
// baseline (speedup 1.0000x reference)
#include <cuda_runtime.h>
#include <cuda_fp16.h>
#include <cstdint>

// ---------------------------------------------------------------------------
// Actor_22625887715353 — round 16: round-13 GEMM core and static schedule
// UNCHANGED (best: 128x128x64, 2 CTAs/SM, fp16 mma.sync, softmax fused in
// G3), with prep folded in as a FINE-GRAINED grid-stride phase (exact
// round-9 block decomposition, 15365 tiny independent blocks) + one global
// barrier (296 resident CTAs). Removes the prep->GEMM launch gap without
// round 15's coarse-item serialization.
// ---------------------------------------------------------------------------

constexpr int BSZ = 4096, IN_DIM = 2048, HID = 2048, H2 = 1024, NHC = 1280;

// ---- device scratch (no cudaMalloc allowed) ----
__device__ __half g_xh[BSZ * IN_DIM];
__device__ __half g_w1h[HID * IN_DIM];     // [N=2048, K=2048]
__device__ __half g_w2h[H2 * HID];         // [N=1024, K=2048]
__device__ __half g_wph[NHC * H2];         // [N=1280, K=1024]
__device__ __half g_h1h[BSZ * HID];
__device__ __half g_h2h[BSZ * H2];
__device__ float g_bpack[NHC];

// sync: [0] global-barrier arrivals | [1..32] cnt1 strips | [33..64] cnt2
constexpr int S_BAR = 0, S_C1 = 1, S_C2 = 33, NSYNC = 65;
__device__ int g_sync[NSYNC];

// ===========================================================================
// Low-level helpers (family-agnostic sm_80+ ISA)
// ===========================================================================
__device__ __forceinline__ uint32_t cvta_s(const void* p) {
    uint32_t a;
    asm("{ .reg .u64 t; cvta.to.shared.u64 t, %1; cvt.u32.u64 %0, t; }" : "=r"(a) : "l"(p));
    return a;
}
__device__ __forceinline__ int ld_acq(const int* p) {
    int v;
    asm volatile("ld.acquire.gpu.global.b32 %0, [%1];" : "=r"(v) : "l"(p) : "memory");
    return v;
}
#define CP16(d, s) asm volatile("cp.async.cg.shared.global [%0], [%1], 16;" :: "r"(d), "l"(s))
#define CP_COMMIT  asm volatile("cp.async.commit_group;")
#define CP_WAIT1   asm volatile("cp.async.wait_group 1;")
#define LDSM4(r0, r1, r2, r3, a) \
    asm volatile("ldmatrix.sync.aligned.m8n8.x4.shared.b16 {%0,%1,%2,%3}, [%4];" \
                 : "=r"(r0), "=r"(r1), "=r"(r2), "=r"(r3) : "r"(a))
#define MMA_F16(d, a, b) \
    asm volatile("mma.sync.aligned.m16n8k16.row.col.f32.f16.f16.f32 " \
                 "{%0,%1,%2,%3},{%4,%5,%6,%7},{%8,%9},{%0,%1,%2,%3};" \
                 : "+f"((d)[0]), "+f"((d)[1]), "+f"((d)[2]), "+f"((d)[3]) \
                 : "r"((a)[0]), "r"((a)[1]), "r"((a)[2]), "r"((a)[3]), \
                   "r"((b)[0]), "r"((b)[1]))

// ===========================================================================
// Tile geometry (rounds 7-13): CTA 128x128x64, 3-stage cp.async, 96 KB smem.
// ===========================================================================
constexpr int BM = 128, BN = 128, BK = 64, STAGES = 3;
constexpr int TB1 = BM * 64;
constexpr int SM_A0 = 0, SM_A1 = TB1, SM_B0 = 2 * TB1, SM_B1 = 3 * TB1;
constexpr int STB = 4 * TB1;                   // 32 KB per stage
constexpr int GEMM_SMEM = STAGES * STB;        // 96 KB

constexpr int NWORK   = 296;                   // 148 SMs x 2 CTAs (all resident)
constexpr int NT_G1   = 512;                   // 32 strips x 16
constexpr int NT_G2   = 256;                   // 32 strips x 8
constexpr int NT_G3   = 320;                   // 32 strips x 10
constexpr int N_ITEMS = NT_G1 + NT_G2 + NT_G3; // 1088

// ---- prep block decomposition (round 9, unchanged granularity) ----
constexpr int PB0 = (BSZ * IN_DIM / 4) / 256;              // 8192 x-cast
constexpr int PB1 = PB0 + (HID / 32) * (IN_DIM / 32);      // +4096 w1^T
constexpr int PB2 = PB1 + (H2 / 32) * (HID / 32);          // +2048 w2^T
constexpr int PB3 = PB2 + 32 * (H2 / 32);                  // +1024 rsu
constexpr int PB4 = PB3 + 32 * (H2 / 32);                  // +1024 lay
constexpr int PB5 = PB4 + (NHC + 255) / 256;               // +5 bias

// One fine prep block (round-9 body). Uniform branch per CTA iteration, so
// the internal __syncthreads are safe under the grid-stride loop.
__device__ __forceinline__ void prep_block(
    char* smem, int b,
    const float* __restrict__ x,  const float* __restrict__ w1,
    const float* __restrict__ w2, const float* __restrict__ wr,
    const float* __restrict__ br, const float* __restrict__ wl,
    const float* __restrict__ bl)
{
    float (*t)[33] = (float(*)[33])smem;
    const int tid = threadIdx.x, tx = tid & 31, ty = tid >> 5;

    if (b < PB0) {                              // ---- cast x (no smem/sync) --
        const int i = (b * 256 + tid) * 4;
        float4 v = *(const float4*)(x + i);
        __half2 a0, a1;
        a0.x = __float2half_rn(v.x); a0.y = __float2half_rn(v.y);
        a1.x = __float2half_rn(v.z); a1.y = __float2half_rn(v.w);
        *(__half2*)(g_xh + i) = a0;
        *(__half2*)(g_xh + i + 2) = a1;
    } else if (b < PB2) {                       // ---- transpose w1 / w2 ----
        const float* in; __half* oh; int R, C, b2;
        if (b < PB1) { in = w1; oh = g_w1h; R = IN_DIM; C = HID; b2 = b - PB0; }
        else         { in = w2; oh = g_w2h; R = HID;    C = H2;  b2 = b - PB1; }
        const int c0 = (b2 % (C / 32)) * 32, r0 = (b2 / (C / 32)) * 32;
#pragma unroll
        for (int k = 0; k < 4; k++)
            t[ty + 8 * k][tx] = in[(size_t)(r0 + ty + 8 * k) * C + c0 + tx];
        __syncthreads();
#pragma unroll
        for (int k = 0; k < 4; k++)
            oh[(size_t)(c0 + ty + 8 * k) * R + r0 + tx] =
                __float2half_rn(t[tx][ty + 8 * k]);
        __syncthreads();
    } else if (b < PB3) {                       // ---- RSU heads ----
        const int b2 = b - PB2;
        const int kh = b2 >> 5, h0 = (b2 & 31) * 32;
        const float* wrk = wr + (size_t)kh * H2 * 32;
#pragma unroll
        for (int k = 0; k < 4; k++)             // t[h_local][r]
            t[ty + 8 * k][tx] = wrk[(size_t)(h0 + ty + 8 * k) * 32 + tx];
        __syncthreads();
#pragma unroll
        for (int k = 0; k < 4; k++) {
            const int j = ty + 8 * k;           // r
            g_wph[(size_t)(kh * 32 + j) * H2 + h0 + tx] = __float2half_rn(t[tx][j]);
        }
        __syncthreads();
    } else if (b < PB4) {                       // ---- LAY heads ----
        const int b2 = b - PB3;
        const int kh = b2 >> 5, h0 = (b2 & 31) * 32;
        t[tid >> 3][tid & 7] = wl[(size_t)kh * H2 * 8 + h0 * 8 + tid];
        __syncthreads();
        g_wph[(size_t)(1024 + kh * 8 + ty) * H2 + h0 + tx] =
            __float2half_rn(t[tx][ty]);
        __syncthreads();
    } else {                                    // ---- bias pack ----
        const int idx = (b - PB4) * 256 + tid;
        if (idx < NHC) g_bpack[idx] = (idx < 1024) ? br[idx] : bl[idx - 1024];
    }
}

// ===========================================================================
// Specialized tile worker (round 13, unchanged): constexpr K per GEMM.
// ===========================================================================
template <int K, bool SMAX>
__device__ __forceinline__ void run_tile(
    uint32_t sb, const __half* __restrict__ A, const __half* __restrict__ B,
    const float* __restrict__ bias, __half* __restrict__ oh,
    float* __restrict__ of, int No, int bm, int bn)
{
    const int tid = threadIdx.x, lane = tid & 31, warp = tid >> 5;
    const int m0w = (warp >> 2) * 64, n0w = (warp & 3) * 32;
    const int lr = tid >> 2, lc = tid & 3;

    const int rA = lane & 15;
    const int hA = lane >> 4;
    const int rB = (lane & 7) + ((lane >> 4) << 3);
    const int hB = (lane >> 3) & 1;

    auto load_stage = [&](int s, int kc) {
        const uint32_t stb = sb + s * STB;
#pragma unroll
        for (int sub = 0; sub < 2; sub++) {
            const int kg = kc * BK + sub * 32 + lc * 8;
            const uint32_t sa = stb + (sub ? SM_A1 : SM_A0);
            const uint32_t sbb = stb + (sub ? SM_B1 : SM_B0);
#pragma unroll
            for (int h = 0; h < 2; h++) {
                const int r = lr + h * 64;
                const uint32_t sw = r * 64 + ((lc ^ ((r >> 1) & 3)) << 4);
                CP16(sa + sw,  A + (size_t)(bm + r) * K + kg);
                CP16(sbb + sw, B + (size_t)(bn + r) * K + kg);
            }
        }
    };

    float acc[4][4][4];
#pragma unroll
    for (int a = 0; a < 4; a++)
#pragma unroll
        for (int b = 0; b < 4; b++)
#pragma unroll
            for (int c = 0; c < 4; c++) acc[a][b][c] = 0.f;

    constexpr int NS = K / BK;
    load_stage(0, 0); CP_COMMIT;
    load_stage(1, 1); CP_COMMIT;

    int s_cur = 0, s_load = 2;
    for (int i = 0; i < NS; i++) {
        CP_WAIT1;
        __syncthreads();
        if (i + 2 < NS) load_stage(s_load, i + 2);
        CP_COMMIT;
        if (++s_load == STAGES) s_load = 0;

        const uint32_t stb = sb + s_cur * STB;
        if (++s_cur == STAGES) s_cur = 0;
#pragma unroll
        for (int sub = 0; sub < 2; sub++) {
            const uint32_t sa = stb + (sub ? SM_A1 : SM_A0);
            const uint32_t sbb = stb + (sub ? SM_B1 : SM_B0);
#pragma unroll
            for (int ks = 0; ks < 2; ks++) {
                uint32_t ahf[4][4], bf[4][2];
#pragma unroll
                for (int mf = 0; mf < 4; mf++) {
                    const int r = m0w + mf * 16 + rA;
                    const uint32_t off = r * 64 + (((ks * 2 + hA) ^ ((r >> 1) & 3)) << 4);
                    LDSM4(ahf[mf][0], ahf[mf][1], ahf[mf][2], ahf[mf][3], sa + off);
                }
#pragma unroll
                for (int p = 0; p < 2; p++) {
                    const int r = n0w + p * 16 + rB;
                    const uint32_t off = r * 64 + (((ks * 2 + hB) ^ ((r >> 1) & 3)) << 4);
                    uint32_t q0, q1, q2, q3;
                    LDSM4(q0, q1, q2, q3, sbb + off);
                    bf[2 * p][0] = q0; bf[2 * p][1] = q1;
                    bf[2 * p + 1][0] = q2; bf[2 * p + 1][1] = q3;
                }
#pragma unroll
                for (int mf = 0; mf < 4; mf++)
#pragma unroll
                    for (int nf = 0; nf < 4; nf++) MMA_F16(acc[mf][nf], ahf[mf], bf[nf]);
            }
        }
    }

    if (!SMAX) {
#pragma unroll
        for (int mf = 0; mf < 4; mf++)
#pragma unroll
            for (int nf = 0; nf < 4; nf++) {
                const int col = bn + n0w + nf * 8 + (lane & 3) * 2;
                const float bx = __ldg(bias + col), by = __ldg(bias + col + 1);
#pragma unroll
                for (int h = 0; h < 2; h++) {
                    const int row = bm + m0w + mf * 16 + (lane >> 2) + h * 8;
                    float v0 = fmaxf(acc[mf][nf][2 * h]     + bx, 0.f);
                    float v1 = fmaxf(acc[mf][nf][2 * h + 1] + by, 0.f);
                    __half2 p;
                    p.x = __float2half_rn(v0); p.y = __float2half_rn(v1);
                    *(__half2*)(oh + (size_t)row * No + col) = p;
                }
            }
    } else {
        const int nbase = bn + n0w;            // warp-uniform
#pragma unroll
        for (int mf = 0; mf < 4; mf++)
#pragma unroll
            for (int h = 0; h < 2; h++) {
                const int row = bm + m0w + mf * 16 + (lane >> 2) + h * 8;
                float* orow = of + (size_t)row * NHC;
                float v[8];
#pragma unroll
                for (int nf = 0; nf < 4; nf++) {
                    const int col = nbase + nf * 8 + (lane & 3) * 2;
                    v[2 * nf]     = acc[mf][nf][2 * h]     + __ldg(bias + col);
                    v[2 * nf + 1] = acc[mf][nf][2 * h + 1] + __ldg(bias + col + 1);
                }
                if (nbase < 1024) {            // RSU head (width 32)
                    float m = v[0];
#pragma unroll
                    for (int j = 1; j < 8; j++) m = fmaxf(m, v[j]);
                    m = fmaxf(m, __shfl_xor_sync(0xffffffffu, m, 1));
                    m = fmaxf(m, __shfl_xor_sync(0xffffffffu, m, 2));
                    float s = 0.f;
#pragma unroll
                    for (int j = 0; j < 8; j++) { v[j] = __expf(v[j] - m); s += v[j]; }
                    s += __shfl_xor_sync(0xffffffffu, s, 1);
                    s += __shfl_xor_sync(0xffffffffu, s, 2);
                    const float inv = 1.f / s;
                    const int k = nbase >> 5;
                    const int ob = (k >> 1) * 80 + (k & 1) * 32 + (lane & 3) * 2;
#pragma unroll
                    for (int nf = 0; nf < 4; nf++)
                        *(float2*)(orow + ob + nf * 8) =
                            make_float2(v[2 * nf] * inv, v[2 * nf + 1] * inv);
                } else {                       // LAY heads (width 8)
#pragma unroll
                    for (int nf = 0; nf < 4; nf++) {
                        float a0 = v[2 * nf], a1 = v[2 * nf + 1];
                        float m = fmaxf(a0, a1);
                        m = fmaxf(m, __shfl_xor_sync(0xffffffffu, m, 1));
                        m = fmaxf(m, __shfl_xor_sync(0xffffffffu, m, 2));
                        const float e0 = __expf(a0 - m), e1 = __expf(a1 - m);
                        float s = e0 + e1;
                        s += __shfl_xor_sync(0xffffffffu, s, 1);
                        s += __shfl_xor_sync(0xffffffffu, s, 2);
                        const float inv = 1.f / s;
                        const int k = (nbase + nf * 8 - 1024) >> 3;
                        const int ob = (k >> 1) * 80 + 64 + (k & 1) * 8 + (lane & 3) * 2;
                        *(float2*)(orow + ob) = make_float2(e0 * inv, e1 * inv);
                    }
                }
            }
    }
}

// ===========================================================================
// Persistent kernel: fine-grained prep (grid-stride) -> global barrier ->
// round-13 static GEMM schedule. All 296 CTAs resident (launch_bounds(256,2)
// caps regs at 128; 2 x 96 KB smem/SM) -> barrier and strip-waits complete.
// ===========================================================================
__global__ __launch_bounds__(256, 2) void fused_all(
    const float* __restrict__ x,  const float* __restrict__ w1,
    const float* __restrict__ b1, const float* __restrict__ w2,
    const float* __restrict__ b2, const float* __restrict__ wr,
    const float* __restrict__ br, const float* __restrict__ wl,
    const float* __restrict__ bl, float* __restrict__ out)
{
    extern __shared__ char smem[];
    const uint32_t sb = cvta_s(smem);
    const int tid = threadIdx.x;

    // ---- Phase A: prep, fine-grained grid-stride (round-9 blocks) ----
    for (int b = blockIdx.x; b < PB5; b += NWORK)
        prep_block(smem, b, x, w1, w2, wr, br, wl, bl);

    // ---- Phase B: global barrier (all prep visible before any GEMM) ----
    __threadfence();
    __syncthreads();
    if (tid == 0) {
        atomicAdd(&g_sync[S_BAR], 1);
        while (ld_acq(&g_sync[S_BAR]) < NWORK) __nanosleep(64);
    }
    __syncthreads();

    // ---- Phase C: round-13 static GEMM schedule ----
    for (int item = blockIdx.x; item < N_ITEMS; item += NWORK) {
        if (item < NT_G1) {
            const int bm = (item >> 4) * BM, bn = (item & 15) * BN;
            __syncthreads();   // smem reuse guard
            run_tile<IN_DIM, false>(sb, g_xh, g_w1h, b1, g_h1h, nullptr, HID, bm, bn);
            __threadfence();
            __syncthreads();
            if (tid == 0) atomicAdd(&g_sync[S_C1 + (bm >> 7)], 1);
        } else if (item < NT_G1 + NT_G2) {
            const int i = item - NT_G1;
            const int bm = (i >> 3) * BM, bn = (i & 7) * BN;
            if (tid == 0) { while (ld_acq(&g_sync[S_C1 + (bm >> 7)]) < 16) __nanosleep(64); }
            __syncthreads();
            run_tile<HID, false>(sb, g_h1h, g_w2h, b2, g_h2h, nullptr, H2, bm, bn);
            __threadfence();
            __syncthreads();
            if (tid == 0) atomicAdd(&g_sync[S_C2 + (bm >> 7)], 1);
        } else {
            const int i = item - NT_G1 - NT_G2;
            const int bm = (i / 10) * BM, bn = (i % 10) * BN;
            if (tid == 0) { while (ld_acq(&g_sync[S_C2 + (bm >> 7)]) < 8) __nanosleep(64); }
            __syncthreads();
            run_tile<H2, true>(sb, g_h2h, g_wph, g_bpack, nullptr, out, NHC, bm, bn);
            __syncthreads();   // protect smem before next item
        }
    }
}

// ===========================================================================
// Host side
// ===========================================================================
extern "C" void kernel_launch(void* const* d_in, const int* in_sizes, int n_in,
                              void* d_out, int out_size)
{
    const float* x  = (const float*)d_in[0];
    const float* w1 = (const float*)d_in[1];
    const float* b1 = (const float*)d_in[2];
    const float* w2 = (const float*)d_in[3];
    const float* b2 = (const float*)d_in[4];
    const float* wr = (const float*)d_in[5];
    const float* br = (const float*)d_in[6];
    const float* wl = (const float*)d_in[7];
    const float* bl = (const float*)d_in[8];
    float* out = (float*)d_out;

    void* syncp;
    cudaGetSymbolAddress(&syncp, g_sync);

    cudaFuncSetAttribute(fused_all,
                         cudaFuncAttributeMaxDynamicSharedMemorySize, GEMM_SMEM);

    // zero barrier + strip counters (captured graph node; no allocation)
    cudaMemsetAsync(syncp, 0, NSYNC * sizeof(int));

    // ONE persistent kernel: prep -> barrier -> GEMM1+GEMM2+GEMM3(+softmax)
    fused_all<<<NWORK, 256, GEMM_SMEM>>>(x, w1, b1, w2, b2, wr, br, wl, bl, out);
}

// round 17
// speedup vs baseline: 1.1222x; 1.1222x over previous
#include <cuda_runtime.h>
#include <cuda_fp16.h>
#include <cstdint>

// ---------------------------------------------------------------------------
// Actor_22625887715353 — round 17: revert to the round-11 optimum (best
// measured: 235.55us). Persistent fused GEMM1+2+3 kernel, 296 resident CTAs,
// STATIC strided tile list (proven to meet the 112-chunk-unit static-schedule
// lower bound), strip-counter dependencies G1->G2->G3, fp16 mma.sync
// 128x128x64 @ 2 CTAs/SM (measured crossbar/tensor co-saturation optimum),
// softmax+scatter fused in G3 epilogue. High-occupancy standalone prep kernel
// (HBM-roofline-bound; in-kernel prep fusion loses 3x to low occupancy).
// Structural alternatives eliminated by rounds 12 (dynamic tickets: phase
// convoying), 14 (64x64 tiles: reg pressure), 15/16 (prep fusion: occupancy).
// ---------------------------------------------------------------------------

constexpr int BSZ = 4096, IN_DIM = 2048, HID = 2048, H2 = 1024, NHC = 1280;

// ---- device scratch (no cudaMalloc allowed) ----
__device__ __half g_xh[BSZ * IN_DIM];
__device__ __half g_w1h[HID * IN_DIM];     // [N=2048, K=2048]
__device__ __half g_w2h[H2 * HID];         // [N=1024, K=2048]
__device__ __half g_wph[NHC * H2];         // [N=1280, K=1024]
__device__ __half g_h1h[BSZ * HID];
__device__ __half g_h2h[BSZ * H2];
__device__ float g_bpack[NHC];
__device__ int   g_cnt1[32], g_cnt2[32];   // h1 / h2 row-strip ready counters

// ===========================================================================
// Low-level helpers (family-agnostic sm_80+ ISA)
// ===========================================================================
__device__ __forceinline__ uint32_t cvta_s(const void* p) {
    uint32_t a;
    asm("{ .reg .u64 t; cvta.to.shared.u64 t, %1; cvt.u32.u64 %0, t; }" : "=r"(a) : "l"(p));
    return a;
}
__device__ __forceinline__ int ld_acq(const int* p) {
    int v;
    asm volatile("ld.acquire.gpu.global.b32 %0, [%1];" : "=r"(v) : "l"(p) : "memory");
    return v;
}
#define CP16(d, s) asm volatile("cp.async.cg.shared.global [%0], [%1], 16;" :: "r"(d), "l"(s))
#define CP_COMMIT  asm volatile("cp.async.commit_group;")
#define CP_WAIT1   asm volatile("cp.async.wait_group 1;")
#define LDSM4(r0, r1, r2, r3, a) \
    asm volatile("ldmatrix.sync.aligned.m8n8.x4.shared.b16 {%0,%1,%2,%3}, [%4];" \
                 : "=r"(r0), "=r"(r1), "=r"(r2), "=r"(r3) : "r"(a))
#define MMA_F16(d, a, b) \
    asm volatile("mma.sync.aligned.m16n8k16.row.col.f32.f16.f16.f32 " \
                 "{%0,%1,%2,%3},{%4,%5,%6,%7},{%8,%9},{%0,%1,%2,%3};" \
                 : "+f"((d)[0]), "+f"((d)[1]), "+f"((d)[2]), "+f"((d)[3]) \
                 : "r"((a)[0]), "r"((a)[1]), "r"((a)[2]), "r"((a)[3]), \
                   "r"((b)[0]), "r"((b)[1]))

// ===========================================================================
// Tile geometry (rounds 7-13): CTA 128x128x64, 3-stage cp.async, 96 KB smem.
// ===========================================================================
constexpr int BM = 128, BN = 128, BK = 64, STAGES = 3;
constexpr int TB1 = BM * 64;
constexpr int SM_A0 = 0, SM_A1 = TB1, SM_B0 = 2 * TB1, SM_B1 = 3 * TB1;
constexpr int STB = 4 * TB1;                   // 32 KB per stage
constexpr int GEMM_SMEM = STAGES * STB;        // 96 KB

constexpr int NWORK   = 296;                   // 148 SMs x 2 CTAs (all resident)
constexpr int NT_G1   = 512;                   // 32 strips x 16
constexpr int NT_G2   = 256;                   // 32 strips x 8
constexpr int NT_G3   = 320;                   // 32 strips x 10
constexpr int N_ITEMS = NT_G1 + NT_G2 + NT_G3; // 1088

__global__ __launch_bounds__(256, 2) void fused_gemms(
    const float* __restrict__ b1, const float* __restrict__ b2,
    float* __restrict__ out)
{
    extern __shared__ char smem[];
    const uint32_t sb = cvta_s(smem);
    const int tid = threadIdx.x, lane = tid & 31, warp = tid >> 5;
    const int m0w = (warp >> 2) * 64, n0w = (warp & 3) * 32;
    const int lr = tid >> 2, lc = tid & 3;

    // ldmatrix lane geometry (validated rounds 3-16)
    const int rA = lane & 15;
    const int hA = lane >> 4;
    const int rB = (lane & 7) + ((lane >> 4) << 3);
    const int hB = (lane >> 3) & 1;

    for (int item = blockIdx.x; item < N_ITEMS; item += NWORK) {
        // ---- decode work item ----
        int gemm, bm, bn, K;
        const __half *A, *B;
        if (item < NT_G1) {
            gemm = 0; bm = (item >> 4) * BM; bn = (item & 15) * BN;
            A = g_xh; B = g_w1h; K = IN_DIM;
        } else if (item < NT_G1 + NT_G2) {
            const int i = item - NT_G1;
            gemm = 1; bm = (i >> 3) * BM; bn = (i & 7) * BN;
            A = g_h1h; B = g_w2h; K = HID;
        } else {
            const int i = item - NT_G1 - NT_G2;
            gemm = 2; bm = (i / 10) * BM; bn = (i % 10) * BN;
            A = g_h2h; B = g_wph; K = H2;
        }

        // ---- dependency wait (strip counters) ----
        if (tid == 0) {
            if (gemm == 1) { while (ld_acq(&g_cnt1[bm >> 7]) < 16) __nanosleep(64); }
            else if (gemm == 2) { while (ld_acq(&g_cnt2[bm >> 7]) < 8) __nanosleep(64); }
        }
        __syncthreads();

        auto load_stage = [&](int s, int kc) {
            const uint32_t stb = sb + s * STB;
#pragma unroll
            for (int sub = 0; sub < 2; sub++) {
                const int kg = kc * BK + sub * 32 + lc * 8;
                const uint32_t sa = stb + (sub ? SM_A1 : SM_A0);
                const uint32_t sbb = stb + (sub ? SM_B1 : SM_B0);
#pragma unroll
                for (int h = 0; h < 2; h++) {
                    const int r = lr + h * 64;
                    const uint32_t sw = r * 64 + ((lc ^ ((r >> 1) & 3)) << 4);
                    CP16(sa + sw,  A + (size_t)(bm + r) * K + kg);
                    CP16(sbb + sw, B + (size_t)(bn + r) * K + kg);
                }
            }
        };

        float acc[4][4][4];
#pragma unroll
        for (int a = 0; a < 4; a++)
#pragma unroll
            for (int b = 0; b < 4; b++)
#pragma unroll
                for (int c = 0; c < 4; c++) acc[a][b][c] = 0.f;

        const int NS = K / BK;
        load_stage(0, 0); CP_COMMIT;
        load_stage(1, 1); CP_COMMIT;

        int s_cur = 0, s_load = 2;
        for (int i = 0; i < NS; i++) {
            CP_WAIT1;
            __syncthreads();
            if (i + 2 < NS) load_stage(s_load, i + 2);
            CP_COMMIT;
            if (++s_load == STAGES) s_load = 0;

            const uint32_t stb = sb + s_cur * STB;
            if (++s_cur == STAGES) s_cur = 0;
#pragma unroll
            for (int sub = 0; sub < 2; sub++) {
                const uint32_t sa = stb + (sub ? SM_A1 : SM_A0);
                const uint32_t sbb = stb + (sub ? SM_B1 : SM_B0);
#pragma unroll
                for (int ks = 0; ks < 2; ks++) {
                    uint32_t ahf[4][4], bf[4][2];
#pragma unroll
                    for (int mf = 0; mf < 4; mf++) {
                        const int r = m0w + mf * 16 + rA;
                        const uint32_t off = r * 64 + (((ks * 2 + hA) ^ ((r >> 1) & 3)) << 4);
                        LDSM4(ahf[mf][0], ahf[mf][1], ahf[mf][2], ahf[mf][3], sa + off);
                    }
#pragma unroll
                    for (int p = 0; p < 2; p++) {
                        const int r = n0w + p * 16 + rB;
                        const uint32_t off = r * 64 + (((ks * 2 + hB) ^ ((r >> 1) & 3)) << 4);
                        uint32_t q0, q1, q2, q3;
                        LDSM4(q0, q1, q2, q3, sbb + off);
                        bf[2 * p][0] = q0; bf[2 * p][1] = q1;
                        bf[2 * p + 1][0] = q2; bf[2 * p + 1][1] = q3;
                    }
#pragma unroll
                    for (int mf = 0; mf < 4; mf++)
#pragma unroll
                        for (int nf = 0; nf < 4; nf++) MMA_F16(acc[mf][nf], ahf[mf], bf[nf]);
                }
            }
        }

        // ---- epilogue ----
        if (gemm < 2) {
            const float* bias = gemm ? b2 : b1;
            __half* oh = gemm ? g_h2h : g_h1h;
            const int No = gemm ? H2 : HID;
#pragma unroll
            for (int mf = 0; mf < 4; mf++)
#pragma unroll
                for (int nf = 0; nf < 4; nf++) {
                    const int col = bn + n0w + nf * 8 + (lane & 3) * 2;
                    const float bx = __ldg(bias + col), by = __ldg(bias + col + 1);
#pragma unroll
                    for (int h = 0; h < 2; h++) {
                        const int row = bm + m0w + mf * 16 + (lane >> 2) + h * 8;
                        float v0 = fmaxf(acc[mf][nf][2 * h]     + bx, 0.f);
                        float v1 = fmaxf(acc[mf][nf][2 * h + 1] + by, 0.f);
                        __half2 p;
                        p.x = __float2half_rn(v0); p.y = __float2half_rn(v1);
                        *(__half2*)(oh + (size_t)row * No + col) = p;
                    }
                }
            // signal strip completion (release)
            __threadfence();
            __syncthreads();
            if (tid == 0) atomicAdd(gemm ? &g_cnt2[bm >> 7] : &g_cnt1[bm >> 7], 1);
        } else {
            // bias + per-head softmax + interleaved scatter (round-8 logic)
            const int nbase = bn + n0w;            // warp-uniform
#pragma unroll
            for (int mf = 0; mf < 4; mf++)
#pragma unroll
                for (int h = 0; h < 2; h++) {
                    const int row = bm + m0w + mf * 16 + (lane >> 2) + h * 8;
                    float* orow = out + (size_t)row * NHC;
                    float v[8];
#pragma unroll
                    for (int nf = 0; nf < 4; nf++) {
                        const int col = nbase + nf * 8 + (lane & 3) * 2;
                        v[2 * nf]     = acc[mf][nf][2 * h]     + __ldg(g_bpack + col);
                        v[2 * nf + 1] = acc[mf][nf][2 * h + 1] + __ldg(g_bpack + col + 1);
                    }
                    if (nbase < 1024) {            // RSU head (width 32)
                        float m = v[0];
#pragma unroll
                        for (int j = 1; j < 8; j++) m = fmaxf(m, v[j]);
                        m = fmaxf(m, __shfl_xor_sync(0xffffffffu, m, 1));
                        m = fmaxf(m, __shfl_xor_sync(0xffffffffu, m, 2));
                        float s = 0.f;
#pragma unroll
                        for (int j = 0; j < 8; j++) { v[j] = __expf(v[j] - m); s += v[j]; }
                        s += __shfl_xor_sync(0xffffffffu, s, 1);
                        s += __shfl_xor_sync(0xffffffffu, s, 2);
                        const float inv = 1.f / s;
                        const int k = nbase >> 5;
                        const int ob = (k >> 1) * 80 + (k & 1) * 32 + (lane & 3) * 2;
#pragma unroll
                        for (int nf = 0; nf < 4; nf++)
                            *(float2*)(orow + ob + nf * 8) =
                                make_float2(v[2 * nf] * inv, v[2 * nf + 1] * inv);
                    } else {                       // LAY heads (width 8)
#pragma unroll
                        for (int nf = 0; nf < 4; nf++) {
                            float a0 = v[2 * nf], a1 = v[2 * nf + 1];
                            float m = fmaxf(a0, a1);
                            m = fmaxf(m, __shfl_xor_sync(0xffffffffu, m, 1));
                            m = fmaxf(m, __shfl_xor_sync(0xffffffffu, m, 2));
                            const float e0 = __expf(a0 - m), e1 = __expf(a1 - m);
                            float s = e0 + e1;
                            s += __shfl_xor_sync(0xffffffffu, s, 1);
                            s += __shfl_xor_sync(0xffffffffu, s, 2);
                            const float inv = 1.f / s;
                            const int k = (nbase + nf * 8 - 1024) >> 3;
                            const int ob = (k >> 1) * 80 + 64 + (k & 1) * 8 + (lane & 3) * 2;
                            *(float2*)(orow + ob) = make_float2(e0 * inv, e1 * inv);
                        }
                    }
                }
            __syncthreads();   // protect smem before next item
        }
    }
}

// ===========================================================================
// Fused prep kernel (round 9, high occupancy) + strip-counter zeroing.
// ===========================================================================
constexpr int PB0 = (BSZ * IN_DIM / 4) / 256;              // 8192
constexpr int PB1 = PB0 + (HID / 32) * (IN_DIM / 32);      // +4096
constexpr int PB2 = PB1 + (H2 / 32) * (HID / 32);          // +2048
constexpr int PB3 = PB2 + 32 * (H2 / 32);                  // +1024 (rsu)
constexpr int PB4 = PB3 + 32 * (H2 / 32);                  // +1024 (lay)
constexpr int PB5 = PB4 + (NHC + 255) / 256;               // +5

__global__ __launch_bounds__(256) void prep_all(
    const float* __restrict__ x,  const float* __restrict__ w1,
    const float* __restrict__ w2, const float* __restrict__ wr,
    const float* __restrict__ br, const float* __restrict__ wl,
    const float* __restrict__ bl)
{
    __shared__ float t[32][33];
    const int b = blockIdx.x, tid = threadIdx.x;
    const int tx = tid & 31, ty = tid >> 5;     // (32, 8)

    if (b < PB0) {                              // ---- cast x ----
        const int i = (b * 256 + tid) * 4;
        float4 v = *(const float4*)(x + i);
        __half2 a0, a1;
        a0.x = __float2half_rn(v.x); a0.y = __float2half_rn(v.y);
        a1.x = __float2half_rn(v.z); a1.y = __float2half_rn(v.w);
        *(__half2*)(g_xh + i) = a0;
        *(__half2*)(g_xh + i + 2) = a1;
    } else if (b < PB2) {                       // ---- transpose w1 / w2 ----
        const float* in; __half* oh; int R, C, b2;
        if (b < PB1) { in = w1; oh = g_w1h; R = IN_DIM; C = HID; b2 = b - PB0; }
        else         { in = w2; oh = g_w2h; R = HID;    C = H2;  b2 = b - PB1; }
        const int c0 = (b2 % (C / 32)) * 32, r0 = (b2 / (C / 32)) * 32;
#pragma unroll
        for (int k = 0; k < 4; k++)
            t[ty + 8 * k][tx] = in[(size_t)(r0 + ty + 8 * k) * C + c0 + tx];
        __syncthreads();
#pragma unroll
        for (int k = 0; k < 4; k++)
            oh[(size_t)(c0 + ty + 8 * k) * R + r0 + tx] =
                __float2half_rn(t[tx][ty + 8 * k]);
    } else if (b < PB3) {                       // ---- RSU heads ----
        const int b2 = b - PB2;
        const int kh = b2 >> 5, h0 = (b2 & 31) * 32;
        const float* wrk = wr + (size_t)kh * H2 * 32;
#pragma unroll
        for (int k = 0; k < 4; k++)             // t[h_local][r]
            t[ty + 8 * k][tx] = wrk[(size_t)(h0 + ty + 8 * k) * 32 + tx];
        __syncthreads();
#pragma unroll
        for (int k = 0; k < 4; k++) {
            const int j = ty + 8 * k;           // r
            g_wph[(size_t)(kh * 32 + j) * H2 + h0 + tx] = __float2half_rn(t[tx][j]);
        }
    } else if (b < PB4) {                       // ---- LAY heads ----
        const int b2 = b - PB3;
        const int kh = b2 >> 5, h0 = (b2 & 31) * 32;
        t[tid >> 3][tid & 7] = wl[(size_t)kh * H2 * 8 + h0 * 8 + tid];
        __syncthreads();
        g_wph[(size_t)(1024 + kh * 8 + ty) * H2 + h0 + tx] =
            __float2half_rn(t[tx][ty]);
    } else {                                    // ---- bias pack + counters ----
        const int idx = (b - PB4) * 256 + tid;
        if (idx < NHC) g_bpack[idx] = (idx < 1024) ? br[idx] : bl[idx - 1024];
        if (b == PB4 && tid < 32) { g_cnt1[tid] = 0; g_cnt2[tid] = 0; }
    }
}

// ===========================================================================
// Host side
// ===========================================================================
extern "C" void kernel_launch(void* const* d_in, const int* in_sizes, int n_in,
                              void* d_out, int out_size)
{
    const float* x  = (const float*)d_in[0];
    const float* w1 = (const float*)d_in[1];
    const float* b1 = (const float*)d_in[2];
    const float* w2 = (const float*)d_in[3];
    const float* b2 = (const float*)d_in[4];
    const float* wr = (const float*)d_in[5];
    const float* br = (const float*)d_in[6];
    const float* wl = (const float*)d_in[7];
    const float* bl = (const float*)d_in[8];
    float* out = (float*)d_out;

    cudaFuncSetAttribute(fused_gemms,
                         cudaFuncAttributeMaxDynamicSharedMemorySize, GEMM_SMEM);

    // all conversions + counter reset in one high-occupancy launch
    prep_all<<<PB5, 256>>>(x, w1, w2, wr, br, wl, bl);

    // persistent fused GEMM1+GEMM2+GEMM3(+softmax) kernel, static schedule
    fused_gemms<<<NWORK, 256, GEMM_SMEM>>>(b1, b2, out);
}